// round 12
// baseline (speedup 1.0000x reference)
#include <cuda_runtime.h>
#include <cuda_fp16.h>
#include <math.h>

#define RW   512
#define NT   180
#define PAD  112
#define PW   736              // padded width
#define RSPLIT 4
#define RCHUNK 128            // RW / RSPLIT
#define IB   514              // interior band rows (texels with a corner in-image)
#define IBP  257              // texel PAIRS per row (IB/2)

// packed half2(im0,im1) images: [layout 0=normal,1=transposed][RW*RW]
__device__ unsigned g_pimg[2][RW * RW];
// combined 2x2 texel table: [layout][PW*PW]; pure-padding texels stay 0 (BSS,
// never written -> deterministic across replays)
// g_q[l][y*PW+x] = { h2(y,x), h2(y,x+1), h2(y+1,x), h2(y+1,x+1) }
__device__ uint4 g_q[2][PW * PW];
// partials interleaved per output element: g_part[i][z]
__device__ float g_part[2 * RW * NT][RSPLIT];

__global__ void __launch_bounds__(256)
pack_kernel(const float* __restrict__ img)
{
    const int idx = blockIdx.x * blockDim.x + threadIdx.x;   // 0 .. RW*RW-1
    const int l   = blockIdx.y;
    const int x   = idx % RW;
    const int y   = idx / RW;
    const int rr = l ? x : y;
    const int cc = l ? y : x;
    const float a = img[(size_t)rr * RW + cc];
    const float b = img[(size_t)(RW * RW) + (size_t)rr * RW + cc];
    __half2 h = __floats2half2_rn(a, b);
    g_pimg[l][y * RW + x] = reinterpret_cast<unsigned&>(h);
}

__global__ void __launch_bounds__(256)
texel_kernel()
{
    const int idx = blockIdx.x * blockDim.x + threadIdx.x;   // 0 .. IBP*IB-1
    if (idx >= IBP * IB) return;
    const int l  = blockIdx.y;
    const int px = (idx % IBP) * 2 + (PAD - 1);
    const int py = idx / IBP + (PAD - 1);
    const int x  = px - PAD;           // -1, 1, 3, ..., 511
    const int y  = py - PAD;

    const unsigned* __restrict__ pim = &g_pimg[l][0];

    unsigned v[2][3] = {{0u,0u,0u},{0u,0u,0u}};
    #pragma unroll
    for (int dy = 0; dy < 2; ++dy) {
        const int yy = y + dy;
        if ((unsigned)yy < (unsigned)RW) {
            const unsigned* row = pim + yy * RW;
            #pragma unroll
            for (int dx = 0; dx < 3; ++dx) {
                const int xx = x + dx;
                if ((unsigned)xx < (unsigned)RW) v[dy][dx] = row[xx];
            }
        }
    }
    uint4* dst = &g_q[l][py * PW + px];
    dst[0] = make_uint4(v[0][0], v[0][1], v[1][0], v[1][1]);
    dst[1] = make_uint4(v[0][1], v[0][2], v[1][1], v[1][2]);
}

__global__ void __launch_bounds__(128)
radon_kernel()
{
    const int c     = blockIdx.x * blockDim.x + threadIdx.x; // 0..511
    const int t     = blockIdx.y;                            // 0..179
    const int rbase = blockIdx.z * RCHUNK;

    float s, ct;
    sincosf((float)t * 0.017453292519943295f, &s, &ct);

    // Pick layout whose contiguous ("fast") coordinate moves most with c.
    const bool T = fabsf(s) > fabsf(ct);
    const float dfc = T ? -s : ct;    // d(fast)/dc
    const float dfr = T ?  ct : s;    // d(fast)/dr
    const float dsc = T ?  ct : -s;   // d(slow)/dc  (|dsc| <= |dsr|)
    const float dsr = T ?  s  : ct;   // d(slow)/dr  (|dsr| >= 0.707)

    // Rounded shear with outer mod-512: lane L sweeps r = (rbase+kL+j)&511.
    // Every lane's slow coordinate stays within +-0.5 of lane 0 except at
    // the single global wrap (~6% of iterations), so warp requests touch
    // <= 2 consecutive texel-rows.  Union over z covers each r once.
    const int   L     = c & 31;
    const float alpha = dsc / dsr;
    const int   kL    = __float2int_rn(-alpha * (float)L);
    const int   base_r = rbase + kL;

    const uint4* __restrict__ buf = &g_q[T ? 1 : 0][0];

    const float u  = (float)c - 255.5f;
    const float bf = fmaf(dfc, u, 255.5f + (float)PAD);   // fast = bf + dfr*v
    const float bs = fmaf(dsc, u, 255.5f + (float)PAD);   // slow = bs + dsr*v

    float acc0 = 0.0f, acc1 = 0.0f;

    #pragma unroll 4
    for (int j = 0; j < RCHUNK; j += 2) {
        __half2 resp[2];
        #pragma unroll
        for (int k = 0; k < 2; ++k) {
            const int   r  = (base_r + j + k) & (RW - 1);
            const float v  = (float)r - 255.5f;
            const float fa = fmaf(dfr, v, bf);
            const float sl = fmaf(dsr, v, bs);

            const float ff = floorf(fa);
            const float fs = floorf(sl);
            const int   fi = (int)ff;
            const int   si = (int)fs;

            const __half2 wf2 = __float2half2_rn(fa - ff);
            const __half2 ws2 = __float2half2_rn(sl - fs);

            const uint4 A = __ldg(buf + si * PW + fi);
            const __half2 a00 = reinterpret_cast<const __half2&>(A.x);
            const __half2 a01 = reinterpret_cast<const __half2&>(A.y);
            const __half2 a10 = reinterpret_cast<const __half2&>(A.z);
            const __half2 a11 = reinterpret_cast<const __half2&>(A.w);

            const __half2 top = __hfma2(wf2, __hsub2(a01, a00), a00);
            const __half2 bot = __hfma2(wf2, __hsub2(a11, a10), a10);
            resp[k] = __hfma2(ws2, __hsub2(bot, top), top);
        }
        const float2 rf = __half22float2(__hadd2(resp[0], resp[1]));
        acc0 += rf.x;
        acc1 += rf.y;
    }

    g_part[(size_t)c * NT + t][blockIdx.z]        = acc0;
    g_part[(size_t)(RW + c) * NT + t][blockIdx.z] = acc1;
}

__global__ void __launch_bounds__(256)
reduce_kernel(float* __restrict__ out)
{
    const int i = blockIdx.x * blockDim.x + threadIdx.x;   // 0 .. 2*RW*NT-1
    const float4 p = reinterpret_cast<const float4*>(g_part)[i];
    out[i] = (p.x + p.y + p.z + p.w) * (1.0f / 512.0f);
}

extern "C" void kernel_launch(void* const* d_in, const int* in_sizes, int n_in,
                              void* d_out, int out_size)
{
    const float* x = (const float*)d_in[0];
    float* out = (float*)d_out;

    pack_kernel<<<dim3((RW * RW) / 256, 2, 1), 256>>>(x);
    texel_kernel<<<dim3((IBP * IB + 255) / 256, 2, 1), 256>>>();

    dim3 block(128, 1, 1);
    dim3 grid(RW / 128, NT, RSPLIT);        // 4 x 180 x 4 = 2880 CTAs
    radon_kernel<<<grid, block>>>();

    reduce_kernel<<<(2 * RW * NT) / 256, 256>>>(out);
}